// round 6
// baseline (speedup 1.0000x reference)
#include <cuda_runtime.h>
#include <cuda_bf16.h>
#include <math.h>

#define BB 8
#define LL 2048
#define DM 512
#define DI 1024
#define DS 16
#define DTR 32
#define CC 32          // time chunks
#define TT 64          // chunk length
#define EPSV 1e-5f

typedef unsigned long long u64;

__device__ __forceinline__ u64 pk2(float lo, float hi) {
    u64 r; asm("mov.b64 %0, {%1, %2};" : "=l"(r) : "f"(lo), "f"(hi)); return r;
}
__device__ __forceinline__ void upk2(u64 v, float& a, float& b) {
    asm("mov.b64 {%0, %1}, %2;" : "=f"(a), "=f"(b) : "l"(v));
}
__device__ __forceinline__ u64 f2fma(u64 a, u64 b, u64 c) {
    u64 d; asm("fma.rn.f32x2 %0, %1, %2, %3;" : "=l"(d) : "l"(a), "l"(b), "l"(c)); return d;
}
__device__ __forceinline__ u64 f2mul(u64 a, u64 b) {
    u64 d; asm("mul.rn.f32x2 %0, %1, %2;" : "=l"(d) : "l"(a), "l"(b)); return d;
}
__device__ __forceinline__ u64 f2add(u64 a, u64 b) {
    u64 d; asm("add.rn.f32x2 %0, %1, %2;" : "=l"(d) : "l"(a), "l"(b)); return d;
}

union F4U2 { float4 f4; u64 u2[2]; };

// packed powers: p[k] = {e1^(2k+1), e1^(2k+2)}
__device__ __forceinline__ void pow16(float e1, u64* p) {
    float e2 = e1 * e1, e4 = e2 * e2, e8 = e4 * e4;
    p[0] = pk2(e1, e2);
    u64 m2 = pk2(e2, e2);
    p[1] = f2mul(p[0], m2);
    u64 m4 = pk2(e4, e4);
    p[2] = f2mul(p[0], m4);
    p[3] = f2mul(p[1], m4);
    u64 m8 = pk2(e8, e8);
    p[4] = f2mul(p[0], m8);
    p[5] = f2mul(p[1], m8);
    p[6] = f2mul(p[2], m8);
    p[7] = f2mul(p[3], m8);
}

// scalar power tree for scan2 (slow-but-tiny kernel)
#define POWTREE(p, e1)                                                          \
    {                                                                           \
        p[0] = (e1);  p[1] = p[0] * p[0];  p[2] = p[1] * p[0];                  \
        p[3] = p[1] * p[1];  p[4] = p[3] * p[0];  p[5] = p[3] * p[1];           \
        p[6] = p[3] * p[2];  p[7] = p[3] * p[3];  p[8] = p[7] * p[0];           \
        p[9] = p[7] * p[1];  p[10] = p[7] * p[2]; p[11] = p[7] * p[3];          \
        p[12] = p[7] * p[4]; p[13] = p[7] * p[5]; p[14] = p[7] * p[6];          \
        p[15] = p[7] * p[7];                                                    \
    }

// conv+silu recompute from halo'd a/c shared arrays (index tt => global t0+tt)
__device__ __forceinline__ float xc_val(const float* shA, const float* shC, int tt,
                                        int tglob, float cw0, float cw1, float cw2,
                                        float cw3, float cwsum, float cb,
                                        float p1d, float p2d, float p3d) {
    float a0 = shA[tt], a1 = shA[tt + 1], a2 = shA[tt + 2], a3 = shA[tt + 3];
    float c0 = shC[tt], c1 = shC[tt + 1], c2 = shC[tt + 2], c3 = shC[tt + 3];
    float sa = fmaf(a0, cw0, fmaf(a1, cw1, fmaf(a2, cw2, a3 * cw3)));
    float sc = fmaf(c0, cw0, fmaf(c1, cw1, fmaf(c2, cw2, c3 * cw3)));
    float sw;
    if (tglob >= 3) sw = cwsum;
    else { sw = cw3; if (tglob >= 1) sw += cw2; if (tglob >= 2) sw += cw1; }
    float pre = fmaf(p1d, sa, fmaf(p2d, sc, fmaf(p3d, sw, cb)));
    return __fdividef(pre, 1.0f + __expf(-pre));
}

// ---------------- scratch (device globals; no runtime allocation) -------------
__device__ float g_scal[8];                 // mw, mb, mww, mwb, mbb
__device__ int   g_fastA;
__device__ float g_p1[2 * DI];
__device__ float g_p2[2 * DI];
__device__ float g_p3[2 * DI];
__device__ float g_weff[DI];
__device__ float g_A[DI * DS];              // -exp(A_log)
__device__ float g_a[BB * LL];
__device__ float g_c[BB * LL];
__device__ float g_dtl[BB * LL * DTR];      // [b][t][32] dt low-rank
__device__ float g_Bt[BB * DS * LL];        // [b][s][t]
__device__ float g_Ct[BB * DS * LL];        // [b][s][t]
__device__ float g_hF[(size_t)BB * CC * DI * DS];   // chunk-local final states
__device__ float g_Ssum[BB * CC * DI];              // chunk dt sums
__device__ float g_H[(size_t)BB * CC * DI * DS];    // incoming state per chunk
__device__ float g_red[4 * BB * LL];                // d-group partial sums

// ---------------- K1: moments of W_in1 / b_in1 --------------------------------
__global__ void k_stats(const float* __restrict__ w, const float* __restrict__ b) {
    __shared__ float sh[5][16];
    int tid = threadIdx.x;               // 512 threads
    float wv = w[tid], bv = b[tid];
    float v[5] = {wv, bv, wv * wv, wv * bv, bv * bv};
#pragma unroll
    for (int j = 0; j < 5; j++) {
#pragma unroll
        for (int o = 16; o > 0; o >>= 1) v[j] += __shfl_xor_sync(0xffffffffu, v[j], o);
    }
    if ((tid & 31) == 0) {
#pragma unroll
        for (int j = 0; j < 5; j++) sh[j][tid >> 5] = v[j];
    }
    if (tid == 0) g_fastA = 1;
    __syncthreads();
    if (tid < 5) {
        float s = 0.f;
#pragma unroll
        for (int k = 0; k < 16; k++) s += sh[tid][k];
        g_scal[tid] = s * (1.0f / DM);
    }
}

// ---------------- K2: p-vectors, w_eff, A, per-token a/c ----------------------
__global__ void k_prep(const float* __restrict__ Win1, const float* __restrict__ bin1,
                       const float* __restrict__ lng,  const float* __restrict__ lnb,
                       const float* __restrict__ Wxz,  const float* __restrict__ Wom,
                       const float* __restrict__ Wout, const float* __restrict__ Alog,
                       const float* __restrict__ x) {
    int idx = blockIdx.x * 256 + threadIdx.x;
    float mw = g_scal[0], mb = g_scal[1], mww = g_scal[2], mwb = g_scal[3], mbb = g_scal[4];
    if (idx < 4 * 2 * DI) {
        int col  = idx >> 2;              // output column 0..2047
        int part = idx & 3;               // d-range split
        float s1 = 0.f, s2 = 0.f, s3 = 0.f;
        for (int d = part * 128; d < part * 128 + 128; d++) {
            float gd = lng[d];
            float u = (Win1[d] - mw) * gd;
            float v = (bin1[d] - mb) * gd;
            float wv = Wxz[d * (2 * DI) + col];
            s1 = fmaf(u, wv, s1);
            s2 = fmaf(v, wv, s2);
            s3 = fmaf(lnb[d], wv, s3);
        }
        s1 += __shfl_xor_sync(0xffffffffu, s1, 1); s1 += __shfl_xor_sync(0xffffffffu, s1, 2);
        s2 += __shfl_xor_sync(0xffffffffu, s2, 1); s2 += __shfl_xor_sync(0xffffffffu, s2, 2);
        s3 += __shfl_xor_sync(0xffffffffu, s3, 1); s3 += __shfl_xor_sync(0xffffffffu, s3, 2);
        if (part == 0) { g_p1[col] = s1; g_p2[col] = s2; g_p3[col] = s3; }
    } else if (idx < 8192 + DI) {
        int j = idx - 8192;
        float s = 0.f;
        for (int m = 0; m < DM; m++) s = fmaf(Wom[j * DM + m], Wout[m], s);
        g_weff[j] = s;
    } else if (idx < 8192 + DI + DI * DS) {
        int i2 = idx - 8192 - DI;
        float av = -expf(Alog[i2]);
        g_A[i2] = av;
        int s = i2 & (DS - 1);
        float expect = -(float)(s + 1);
        if (fabsf(av - expect) > 1e-4f * (float)(s + 1)) atomicAnd(&g_fastA, 0);
    } else if (idx < 8192 + DI + DI * DS + BB * LL) {
        int i2 = idx - 8192 - DI - DI * DS;
        float xv = x[i2];
        float varw = mww - mw * mw;
        float cwb  = mwb - mw * mb;
        float varb = mbb - mb * mb;
        float var  = fmaf(xv * xv, varw, fmaf(2.0f * xv, cwb, varb));
        float s    = rsqrtf(var + EPSV);
        g_a[i2] = xv * s;
        g_c[i2] = s;
    }
}

// ---------------- K3: (xc recompute) @ W_xp -> dt_low, B^T, C^T ---------------
__global__ __launch_bounds__(256) void k_proj(const float* __restrict__ Wxp,
                                              const float* __restrict__ convw,
                                              const float* __restrict__ convb) {
    int blk = blockIdx.x;                    // 256 blocks
    int b  = blk >> 5;
    int t0 = (blk & 31) * 64;
    __shared__ float At[32][68];
    __shared__ float Bt_[32][64];
    __shared__ float shA[67], shC[67];
    __shared__ float chc[32][8];             // cw0..3, cb, p1, p2, p3
    int tid = threadIdx.x;
    int tx = tid & 15, ty = tid >> 4;
    if (tid < 67) {
        int gt = t0 - 3 + tid;
        shA[tid] = (gt >= 0) ? g_a[b * LL + gt] : 0.f;
        shC[tid] = (gt >= 0) ? g_c[b * LL + gt] : 0.f;
    }
    u64 acc2[2][4];
#pragma unroll
    for (int i = 0; i < 2; i++)
#pragma unroll
        for (int j = 0; j < 4; j++) acc2[i][j] = 0ULL;

    for (int k0 = 0; k0 < DI; k0 += 32) {
        __syncthreads();
        // stage channel constants (32 ch x 8 floats)
        {
            int chx = tid >> 3, f = tid & 7;
            int ch = k0 + chx;
            float v;
            if (f < 4)      v = convw[ch * 4 + f];
            else if (f == 4) v = convb[ch];
            else if (f == 5) v = g_p1[ch];
            else if (f == 6) v = g_p2[ch];
            else             v = g_p3[ch];
            chc[chx][f] = v;
        }
        // stage W tile
#pragma unroll
        for (int i = 0; i < 2; i++) {
            int q = tid + i * 256;           // q < 512
            int kk = q >> 4, n4 = q & 15;
            float4 v = *(const float4*)(Wxp + (size_t)(k0 + kk) * 64 + n4 * 4);
            *(float4*)&Bt_[kk][n4 * 4] = v;
        }
        __syncthreads();
        // fill At by recomputing xc: thread owns one kk, 8 consecutive t
        {
            int kk = tid >> 3, tseg = tid & 7;
            float cw0 = chc[kk][0], cw1 = chc[kk][1], cw2 = chc[kk][2], cw3 = chc[kk][3];
            float cb = chc[kk][4], p1d = chc[kk][5], p2d = chc[kk][6], p3d = chc[kk][7];
            float cwsum = cw0 + cw1 + cw2 + cw3;
#pragma unroll
            for (int u = 0; u < 8; u++) {
                int tt = tseg * 8 + u;
                At[kk][tt] = xc_val(shA, shC, tt, t0 + tt, cw0, cw1, cw2, cw3,
                                    cwsum, cb, p1d, p2d, p3d);
            }
        }
        __syncthreads();
#pragma unroll
        for (int kk = 0; kk < 32; kk++) {
            float4 bv = *(float4*)&Bt_[kk][tx * 4];
            u64 bx = pk2(bv.x, bv.x), by = pk2(bv.y, bv.y);
            u64 bz = pk2(bv.z, bv.z), bw = pk2(bv.w, bv.w);
            u64 av0 = *(const u64*)&At[kk][ty * 4];
            u64 av1 = *(const u64*)&At[kk][ty * 4 + 2];
            acc2[0][0] = f2fma(av0, bx, acc2[0][0]);
            acc2[0][1] = f2fma(av0, by, acc2[0][1]);
            acc2[0][2] = f2fma(av0, bz, acc2[0][2]);
            acc2[0][3] = f2fma(av0, bw, acc2[0][3]);
            acc2[1][0] = f2fma(av1, bx, acc2[1][0]);
            acc2[1][1] = f2fma(av1, by, acc2[1][1]);
            acc2[1][2] = f2fma(av1, bz, acc2[1][2]);
            acc2[1][3] = f2fma(av1, bw, acc2[1][3]);
        }
    }
    float acc[4][4];
#pragma unroll
    for (int i2 = 0; i2 < 2; i2++)
#pragma unroll
        for (int j = 0; j < 4; j++)
            upk2(acc2[i2][j], acc[i2 * 2][j], acc[i2 * 2 + 1][j]);
#pragma unroll
    for (int i = 0; i < 4; i++) {
        int t = t0 + ty * 4 + i;
        if (tx < 8) {
            *(float4*)(g_dtl + ((size_t)(b * LL + t)) * DTR + tx * 4) =
                make_float4(acc[i][0], acc[i][1], acc[i][2], acc[i][3]);
        } else {
#pragma unroll
            for (int j = 0; j < 4; j++) {
                int n = tx * 4 + j;
                if (n < 48) g_Bt[((size_t)(b * DS + n - 32)) * LL + t] = acc[i][j];
                else        g_Ct[((size_t)(b * DS + n - 48)) * LL + t] = acc[i][j];
            }
        }
    }
}

// ---------------- K4: chunk-local scan (dt + xc recomputed), emit hF/Ssum -----
__global__ __launch_bounds__(256) void k_scan1(const float* __restrict__ Wdt,
                                               const float* __restrict__ bdt,
                                               const float* __restrict__ convw,
                                               const float* __restrict__ convb) {
    int blk = blockIdx.x;                // 1024 = b(8) x c(32) x dg(4)
    int b  = blk >> 7;
    int c  = (blk >> 2) & 31;
    int dg = blk & 3;
    int tid = threadIdx.x;
    int d  = dg * 256 + tid;
    int t0 = c * TT;

    __shared__ float sdtl[TT][32];
    __shared__ float Bs[TT][DS];
    __shared__ float shA[TT + 3], shC[TT + 3];

    {
        const float4* src = (const float4*)(g_dtl + ((size_t)(b * LL + t0)) * DTR);
        float4* dst = (float4*)&sdtl[0][0];
        for (int i = tid; i < TT * 32 / 4; i += 256) dst[i] = src[i];
        for (int i = tid; i < TT * DS; i += 256) {
            int s = i >> 6, t = i & 63;
            Bs[t][s] = g_Bt[((size_t)b * DS + s) * LL + t0 + t];
        }
        if (tid < TT + 3) {
            int gt = t0 - 3 + tid;
            shA[tid] = (gt >= 0) ? g_a[b * LL + gt] : 0.f;
            shC[tid] = (gt >= 0) ? g_c[b * LL + gt] : 0.f;
        }
    }

    u64 w2[16];
#pragma unroll
    for (int k = 0; k < 16; k++)
        w2[k] = pk2(Wdt[(size_t)(2 * k) * DI + d], Wdt[(size_t)(2 * k + 1) * DI + d]);
    float bd = bdt[d];
    float4 cw = *(const float4*)(convw + d * 4);
    float cb = convb[d];
    float cwsum = cw.x + cw.y + cw.z + cw.w;
    float p1d = g_p1[d], p2d = g_p2[d], p3d = g_p3[d];
    int fast = g_fastA;
    float Areg[16];
    if (!fast) {
#pragma unroll
        for (int s = 0; s < 16; s++) Areg[s] = g_A[d * DS + s];
    }
    __syncthreads();

    u64 h2[8];
#pragma unroll
    for (int k = 0; k < 8; k++) h2[k] = 0ULL;
    float S = 0.f;

#pragma unroll 2
    for (int tt = 0; tt < TT; tt++) {
        const float4* vp = (const float4*)&sdtl[tt][0];
        F4U2 q0, q1, q2, q3, q4, q5, q6, q7;
        q0.f4 = vp[0]; q1.f4 = vp[1]; q2.f4 = vp[2]; q3.f4 = vp[3];
        q4.f4 = vp[4]; q5.f4 = vp[5]; q6.f4 = vp[6]; q7.f4 = vp[7];
        u64 ac0 = f2mul(q0.u2[0], w2[0]);
        u64 ac1 = f2mul(q0.u2[1], w2[1]);
        ac0 = f2fma(q1.u2[0], w2[2], ac0);
        ac1 = f2fma(q1.u2[1], w2[3], ac1);
        ac0 = f2fma(q2.u2[0], w2[4], ac0);
        ac1 = f2fma(q2.u2[1], w2[5], ac1);
        ac0 = f2fma(q3.u2[0], w2[6], ac0);
        ac1 = f2fma(q3.u2[1], w2[7], ac1);
        ac0 = f2fma(q4.u2[0], w2[8], ac0);
        ac1 = f2fma(q4.u2[1], w2[9], ac1);
        ac0 = f2fma(q5.u2[0], w2[10], ac0);
        ac1 = f2fma(q5.u2[1], w2[11], ac1);
        ac0 = f2fma(q6.u2[0], w2[12], ac0);
        ac1 = f2fma(q6.u2[1], w2[13], ac1);
        ac0 = f2fma(q7.u2[0], w2[14], ac0);
        ac1 = f2fma(q7.u2[1], w2[15], ac1);
        u64 acs = f2add(ac0, ac1);
        float alo, ahi;
        upk2(acs, alo, ahi);
        float draw = alo + ahi + bd;
        float dtv = (draw > 20.0f) ? draw : log1pf(__expf(draw));
        S += dtv;
        float xcc = xc_val(shA, shC, tt, t0 + tt, cw.x, cw.y, cw.z, cw.w,
                           cwsum, cb, p1d, p2d, p3d);
        float dx = dtv * xcc;
        u64 dx2 = pk2(dx, dx);
        u64 p2r[8];
        if (fast) {
            pow16(__expf(-dtv), p2r);
        } else {
            float ps[16];
#pragma unroll
            for (int s = 0; s < 16; s++) ps[s] = __expf(dtv * Areg[s]);
#pragma unroll
            for (int k = 0; k < 8; k++) p2r[k] = pk2(ps[2 * k], ps[2 * k + 1]);
        }
        const float4* bp = (const float4*)&Bs[tt][0];
        F4U2 B0, B1, B2, B3;
        B0.f4 = bp[0]; B1.f4 = bp[1]; B2.f4 = bp[2]; B3.f4 = bp[3];
        h2[0] = f2fma(h2[0], p2r[0], f2mul(dx2, B0.u2[0]));
        h2[1] = f2fma(h2[1], p2r[1], f2mul(dx2, B0.u2[1]));
        h2[2] = f2fma(h2[2], p2r[2], f2mul(dx2, B1.u2[0]));
        h2[3] = f2fma(h2[3], p2r[3], f2mul(dx2, B1.u2[1]));
        h2[4] = f2fma(h2[4], p2r[4], f2mul(dx2, B2.u2[0]));
        h2[5] = f2fma(h2[5], p2r[5], f2mul(dx2, B2.u2[1]));
        h2[6] = f2fma(h2[6], p2r[6], f2mul(dx2, B3.u2[0]));
        h2[7] = f2fma(h2[7], p2r[7], f2mul(dx2, B3.u2[1]));
    }
    float* o = g_hF + (((size_t)b * CC + c) * DI + d) * DS;
    F4U2 o0, o1, o2, o3;
    o0.u2[0] = h2[0]; o0.u2[1] = h2[1];
    o1.u2[0] = h2[2]; o1.u2[1] = h2[3];
    o2.u2[0] = h2[4]; o2.u2[1] = h2[5];
    o3.u2[0] = h2[6]; o3.u2[1] = h2[7];
    *(float4*)(o + 0)  = o0.f4;
    *(float4*)(o + 4)  = o1.f4;
    *(float4*)(o + 8)  = o2.f4;
    *(float4*)(o + 12) = o3.f4;
    g_Ssum[((size_t)b * CC + c) * DI + d] = S;
}

// ---------------- K5: propagate states across chunks --------------------------
__global__ __launch_bounds__(256) void k_scan2(void) {
    int idx = blockIdx.x * 256 + threadIdx.x;     // < 8192
    int b = idx >> 10;
    int d = idx & (DI - 1);
    int fast = g_fastA;
    float Areg[16];
    if (!fast) {
#pragma unroll
        for (int s = 0; s < 16; s++) Areg[s] = g_A[d * DS + s];
    }
    float H[16];
#pragma unroll
    for (int s = 0; s < 16; s++) H[s] = 0.f;
#pragma unroll 4
    for (int c = 0; c < CC; c++) {
        float* o = g_H + (((size_t)b * CC + c) * DI + d) * DS;
        *(float4*)(o + 0)  = make_float4(H[0], H[1], H[2], H[3]);
        *(float4*)(o + 4)  = make_float4(H[4], H[5], H[6], H[7]);
        *(float4*)(o + 8)  = make_float4(H[8], H[9], H[10], H[11]);
        *(float4*)(o + 12) = make_float4(H[12], H[13], H[14], H[15]);
        float S = g_Ssum[((size_t)b * CC + c) * DI + d];
        float p[16];
        if (fast) {
            float e1 = __expf(-S);
            POWTREE(p, e1)
        } else {
#pragma unroll
            for (int s = 0; s < 16; s++) p[s] = __expf(S * Areg[s]);
        }
        const float* f = g_hF + (((size_t)b * CC + c) * DI + d) * DS;
        float4 f0 = *(const float4*)(f + 0), f1 = *(const float4*)(f + 4);
        float4 f2 = *(const float4*)(f + 8), f3 = *(const float4*)(f + 12);
        H[0]  = fmaf(H[0],  p[0],  f0.x);  H[1]  = fmaf(H[1],  p[1],  f0.y);
        H[2]  = fmaf(H[2],  p[2],  f0.z);  H[3]  = fmaf(H[3],  p[3],  f0.w);
        H[4]  = fmaf(H[4],  p[4],  f1.x);  H[5]  = fmaf(H[5],  p[5],  f1.y);
        H[6]  = fmaf(H[6],  p[6],  f1.z);  H[7]  = fmaf(H[7],  p[7],  f1.w);
        H[8]  = fmaf(H[8],  p[8],  f2.x);  H[9]  = fmaf(H[9],  p[9],  f2.y);
        H[10] = fmaf(H[10], p[10], f2.z);  H[11] = fmaf(H[11], p[11], f2.w);
        H[12] = fmaf(H[12], p[12], f3.x);  H[13] = fmaf(H[13], p[13], f3.y);
        H[14] = fmaf(H[14], p[14], f3.z);  H[15] = fmaf(H[15], p[15], f3.w);
    }
}

// ---------------- K6: full scan per chunk + gate + fused d-reduction ----------
__global__ __launch_bounds__(256) void k_scan3(const float* __restrict__ Wdt,
                                               const float* __restrict__ bdt,
                                               const float* __restrict__ convw,
                                               const float* __restrict__ convb,
                                               const float* __restrict__ Dskip) {
    int blk = blockIdx.x;                // 1024 = b(8) x c(32) x dg(4)
    int b  = blk >> 7;
    int c  = (blk >> 2) & 31;
    int dg = blk & 3;
    int tid = threadIdx.x;
    int d  = dg * 256 + tid;
    int t0 = c * TT;
    int lane = tid & 31;
    int warp = tid >> 5;

    __shared__ float sdtl[TT][32];
    __shared__ float Bs[TT][DS];
    __shared__ float Cs[TT][DS];
    __shared__ float shA[TT + 3], shC[TT + 3];
    __shared__ float sred[8][TT];

    {
        const float4* src = (const float4*)(g_dtl + ((size_t)(b * LL + t0)) * DTR);
        float4* dst = (float4*)&sdtl[0][0];
        for (int i = tid; i < TT * 32 / 4; i += 256) dst[i] = src[i];
        for (int i = tid; i < 2 * TT * DS; i += 256) {
            int half = i >> 10;
            int j = i & 1023;
            int s = j >> 6, t = j & 63;
            float v = half ? g_Ct[((size_t)b * DS + s) * LL + t0 + t]
                           : g_Bt[((size_t)b * DS + s) * LL + t0 + t];
            (half ? Cs : Bs)[t][s] = v;
        }
        if (tid < TT + 3) {
            int gt = t0 - 3 + tid;
            shA[tid] = (gt >= 0) ? g_a[b * LL + gt] : 0.f;
            shC[tid] = (gt >= 0) ? g_c[b * LL + gt] : 0.f;
        }
    }

    u64 w2[16];
#pragma unroll
    for (int k = 0; k < 16; k++)
        w2[k] = pk2(Wdt[(size_t)(2 * k) * DI + d], Wdt[(size_t)(2 * k + 1) * DI + d]);
    float bd = bdt[d];
    float4 cw = *(const float4*)(convw + d * 4);
    float cb = convb[d];
    float cwsum = cw.x + cw.y + cw.z + cw.w;
    float p1d = g_p1[d], p2d = g_p2[d], p3d = g_p3[d];
    float p1z = g_p1[DI + d], p2z = g_p2[DI + d], p3z = g_p3[DI + d];
    float we = g_weff[d];
    float Dd = Dskip[d];
    int fast = g_fastA;
    float Areg[16];
    if (!fast) {
#pragma unroll
        for (int s = 0; s < 16; s++) Areg[s] = g_A[d * DS + s];
    }
    u64 h2[8];
    {
        const float* Hp = g_H + (((size_t)b * CC + c) * DI + d) * DS;
        F4U2 H0, H1, H2, H3;
        H0.f4 = *(const float4*)(Hp + 0);
        H1.f4 = *(const float4*)(Hp + 4);
        H2.f4 = *(const float4*)(Hp + 8);
        H3.f4 = *(const float4*)(Hp + 12);
        h2[0] = H0.u2[0]; h2[1] = H0.u2[1];
        h2[2] = H1.u2[0]; h2[3] = H1.u2[1];
        h2[4] = H2.u2[0]; h2[5] = H2.u2[1];
        h2[6] = H3.u2[0]; h2[7] = H3.u2[1];
    }
    __syncthreads();

#pragma unroll 2
    for (int tt = 0; tt < TT; tt++) {
        const float4* vp = (const float4*)&sdtl[tt][0];
        F4U2 q0, q1, q2, q3, q4, q5, q6, q7;
        q0.f4 = vp[0]; q1.f4 = vp[1]; q2.f4 = vp[2]; q3.f4 = vp[3];
        q4.f4 = vp[4]; q5.f4 = vp[5]; q6.f4 = vp[6]; q7.f4 = vp[7];
        u64 ac0 = f2mul(q0.u2[0], w2[0]);
        u64 ac1 = f2mul(q0.u2[1], w2[1]);
        ac0 = f2fma(q1.u2[0], w2[2], ac0);
        ac1 = f2fma(q1.u2[1], w2[3], ac1);
        ac0 = f2fma(q2.u2[0], w2[4], ac0);
        ac1 = f2fma(q2.u2[1], w2[5], ac1);
        ac0 = f2fma(q3.u2[0], w2[6], ac0);
        ac1 = f2fma(q3.u2[1], w2[7], ac1);
        ac0 = f2fma(q4.u2[0], w2[8], ac0);
        ac1 = f2fma(q4.u2[1], w2[9], ac1);
        ac0 = f2fma(q5.u2[0], w2[10], ac0);
        ac1 = f2fma(q5.u2[1], w2[11], ac1);
        ac0 = f2fma(q6.u2[0], w2[12], ac0);
        ac1 = f2fma(q6.u2[1], w2[13], ac1);
        ac0 = f2fma(q7.u2[0], w2[14], ac0);
        ac1 = f2fma(q7.u2[1], w2[15], ac1);
        u64 acs = f2add(ac0, ac1);
        float alo, ahi;
        upk2(acs, alo, ahi);
        float draw = alo + ahi + bd;
        float dtv = (draw > 20.0f) ? draw : log1pf(__expf(draw));
        float xcc = xc_val(shA, shC, tt, t0 + tt, cw.x, cw.y, cw.z, cw.w,
                           cwsum, cb, p1d, p2d, p3d);
        float dx = dtv * xcc;
        u64 dx2 = pk2(dx, dx);
        u64 p2r[8];
        if (fast) {
            pow16(__expf(-dtv), p2r);
        } else {
            float ps[16];
#pragma unroll
            for (int s = 0; s < 16; s++) ps[s] = __expf(dtv * Areg[s]);
#pragma unroll
            for (int k = 0; k < 8; k++) p2r[k] = pk2(ps[2 * k], ps[2 * k + 1]);
        }
        const float4* bp = (const float4*)&Bs[tt][0];
        const float4* cp = (const float4*)&Cs[tt][0];
        F4U2 B0, B1, B2, B3, C0, C1, C2, C3;
        B0.f4 = bp[0]; B1.f4 = bp[1]; B2.f4 = bp[2]; B3.f4 = bp[3];
        C0.f4 = cp[0]; C1.f4 = cp[1]; C2.f4 = cp[2]; C3.f4 = cp[3];
        h2[0] = f2fma(h2[0], p2r[0], f2mul(dx2, B0.u2[0]));
        h2[1] = f2fma(h2[1], p2r[1], f2mul(dx2, B0.u2[1]));
        h2[2] = f2fma(h2[2], p2r[2], f2mul(dx2, B1.u2[0]));
        h2[3] = f2fma(h2[3], p2r[3], f2mul(dx2, B1.u2[1]));
        h2[4] = f2fma(h2[4], p2r[4], f2mul(dx2, B2.u2[0]));
        h2[5] = f2fma(h2[5], p2r[5], f2mul(dx2, B2.u2[1]));
        h2[6] = f2fma(h2[6], p2r[6], f2mul(dx2, B3.u2[0]));
        h2[7] = f2fma(h2[7], p2r[7], f2mul(dx2, B3.u2[1]));
        u64 y2 = f2mul(h2[0], C0.u2[0]);
        y2 = f2fma(h2[1], C0.u2[1], y2);
        y2 = f2fma(h2[2], C1.u2[0], y2);
        y2 = f2fma(h2[3], C1.u2[1], y2);
        y2 = f2fma(h2[4], C2.u2[0], y2);
        y2 = f2fma(h2[5], C2.u2[1], y2);
        y2 = f2fma(h2[6], C3.u2[0], y2);
        y2 = f2fma(h2[7], C3.u2[1], y2);
        float ylo, yhi;
        upk2(y2, ylo, yhi);
        float y = ylo + yhi;
        float z  = fmaf(shA[tt + 3], p1z, fmaf(shC[tt + 3], p2z, p3z));
        float zs = __fdividef(z, 1.0f + __expf(-z)) * we;
        float outv = fmaf(Dd, xcc, y) * zs;
#pragma unroll
        for (int o = 16; o > 0; o >>= 1) outv += __shfl_xor_sync(0xffffffffu, outv, o);
        if (lane == 0) sred[warp][tt] = outv;
    }
    __syncthreads();
    if (tid < TT) {
        float s = 0.f;
#pragma unroll
        for (int w = 0; w < 8; w++) s += sred[w][tid];
        g_red[dg * (BB * LL) + b * LL + t0 + tid] = s;
    }
}

// ---------------- K7: combine 4 d-group partials + residual -------------------
__global__ __launch_bounds__(256) void k_fin2(const float* __restrict__ x,
                                              const float* __restrict__ bout,
                                              float* __restrict__ out) {
    int row = blockIdx.x * 256 + threadIdx.x;   // < 16384
    float s = g_red[row] + g_red[BB * LL + row] + g_red[2 * BB * LL + row] +
              g_red[3 * BB * LL + row];
    out[row] = s + bout[0] + x[row];
}

// ---------------- launch ------------------------------------------------------
extern "C" void kernel_launch(void* const* d_in, const int* in_sizes, int n_in,
                              void* d_out, int out_size) {
    const float* x      = (const float*)d_in[0];
    const float* W_in1  = (const float*)d_in[1];
    const float* b_in1  = (const float*)d_in[2];
    const float* ln_g   = (const float*)d_in[3];
    const float* ln_b   = (const float*)d_in[4];
    const float* W_xz   = (const float*)d_in[5];
    const float* conv_w = (const float*)d_in[6];
    const float* conv_b = (const float*)d_in[7];
    const float* W_xp   = (const float*)d_in[8];
    const float* W_dt   = (const float*)d_in[9];
    const float* b_dt   = (const float*)d_in[10];
    const float* A_log  = (const float*)d_in[11];
    const float* D_skip = (const float*)d_in[12];
    const float* W_om   = (const float*)d_in[13];
    const float* W_out  = (const float*)d_in[14];
    const float* b_out  = (const float*)d_in[15];
    float* out = (float*)d_out;

    k_stats<<<1, 512>>>(W_in1, b_in1);
    k_prep<<<164, 256>>>(W_in1, b_in1, ln_g, ln_b, W_xz, W_om, W_out, A_log, x);
    k_proj<<<256, 256>>>(W_xp, conv_w, conv_b);
    k_scan1<<<1024, 256>>>(W_dt, b_dt, conv_w, conv_b);
    k_scan2<<<32, 256>>>();
    k_scan3<<<1024, 256>>>(W_dt, b_dt, conv_w, conv_b, D_skip);
    k_fin2<<<64, 256>>>(x, b_out, out);
}